// round 8
// baseline (speedup 1.0000x reference)
#include <cuda_runtime.h>
#include <cuda_bf16.h>
#include <cstdint>

// LengthRegulator: out[b, t, :] = phoneme[b, tok(b,t), :]
// tok(b,t) = searchsorted_right(inclusive_cumsum(durations[b,:]), t), clip N-1.
// Shapes (fixed): B=16, N=256, D=512, T=2048. float32.
//
// Strategy: dedup-loaded rows via small TMA loads, replicate runs in smem,
// then ONE 64KB bulk TMA store per block (32 frames). Minimizes both LTS
// read traffic and TMA per-op overhead; payload never touches the LSU/L1
// on the store side.

#define LR_B 16
#define LR_N 256
#define LR_D 512
#define LR_T 2048
#define FPB 32                        // frames per block
#define THREADS 256
#define ROW_BYTES (LR_D * 4)          // 2048 B per frame
#define STAGE_BYTES (FPB * ROW_BYTES) // 64 KB staging

__device__ __forceinline__ uint32_t smem_u32(const void* p) {
    uint32_t a;
    asm("{ .reg .u64 t; cvta.to.shared.u64 t, %1; cvt.u32.u64 %0, t; }"
        : "=r"(a) : "l"(p));
    return a;
}

__global__ __launch_bounds__(THREADS)
void length_regulator_bulk(const char* __restrict__ phoneme,
                           const int* __restrict__ durations,
                           char* __restrict__ out)
{
    extern __shared__ __align__(128) char s_rows[];   // FPB * ROW_BYTES
    __shared__ int s_ends[LR_N];
    __shared__ int s_lead[FPB];
    __shared__ __align__(8) unsigned long long s_mbar;

    const int b = blockIdx.y;
    const int frame_base = blockIdx.x * FPB;
    const int tid = threadIdx.x;
    const uint32_t mbar = smem_u32(&s_mbar);

    if (tid < 32) {
        const int lane = tid;
        if (lane == 0) {
            asm volatile("mbarrier.init.shared.b64 [%0], %1;"
                         :: "r"(mbar), "r"(1u) : "memory");
        }
        // 1) shuffle scan: lane owns durations[8L..8L+7]
        const int4* drow = (const int4*)(durations + b * LR_N);
        int4 a = drow[lane * 2 + 0];
        int4 c = drow[lane * 2 + 1];
        int e0 = a.x;
        int e1 = e0 + a.y;
        int e2 = e1 + a.z;
        int e3 = e2 + a.w;
        int e4 = e3 + c.x;
        int e5 = e4 + c.y;
        int e6 = e5 + c.z;
        int e7 = e6 + c.w;
        int x = e7;
        #pragma unroll
        for (int off = 1; off < 32; off <<= 1) {
            int y = __shfl_up_sync(0xffffffffu, x, off);
            if (lane >= off) x += y;
        }
        const int excl = x - e7;
        s_ends[lane * 8 + 0] = e0 + excl;
        s_ends[lane * 8 + 1] = e1 + excl;
        s_ends[lane * 8 + 2] = e2 + excl;
        s_ends[lane * 8 + 3] = e3 + excl;
        s_ends[lane * 8 + 4] = e4 + excl;
        s_ends[lane * 8 + 5] = e5 + excl;
        s_ends[lane * 8 + 6] = e6 + excl;
        s_ends[lane * 8 + 7] = e7 + excl;
        __syncwarp();

        // 2) lane = frame: first n with ends[n] > t
        const int t = frame_base + lane;
        int lo = 0, hi = LR_N;
        #pragma unroll
        for (int it = 0; it < 9; ++it) {
            if (lo < hi) {
                int mid = (lo + hi) >> 1;
                if (s_ends[mid] > t) hi = mid; else lo = mid + 1;
            }
        }
        const int tok = (lo < LR_N) ? lo : (LR_N - 1);

        // 3) run-leader dedupe
        const int prev_tok = __shfl_up_sync(0xffffffffu, tok, 1);
        const bool is_new = (lane == 0) || (tok != prev_tok);
        const uint32_t new_mask = __ballot_sync(0xffffffffu, is_new);
        const int leader = 31 - __clz(new_mask & ((2u << lane) - 1));
        s_lead[lane] = leader;
        const int nslots = __popc(new_mask);

        // 4) TMA loads: one 2KB load per distinct row, into the leader's slot
        if (lane == 0) {
            asm volatile("mbarrier.arrive.expect_tx.shared.b64 _, [%0], %1;"
                         :: "r"(mbar), "r"((uint32_t)(nslots * ROW_BYTES)) : "memory");
        }
        __syncwarp();
        if (is_new) {
            const char* src = phoneme + ((size_t)b * LR_N + tok) * ROW_BYTES;
            const uint32_t dst = smem_u32(s_rows) + (uint32_t)(lane * ROW_BYTES);
            asm volatile(
                "cp.async.bulk.shared::cluster.global.mbarrier::complete_tx::bytes "
                "[%0], [%1], %2, [%3];"
                :: "r"(dst), "l"(src), "r"((uint32_t)ROW_BYTES), "r"(mbar)
                : "memory");
        }
    }
    __syncthreads();

    // 5) all threads wait for loads
    {
        uint32_t done;
        do {
            asm volatile(
                "{\n\t.reg .pred p;\n\t"
                "mbarrier.try_wait.parity.shared.b64 p, [%1], %2;\n\t"
                "selp.b32 %0, 1, 0, p;\n\t}"
                : "=r"(done) : "r"(mbar), "r"(0u) : "memory");
        } while (!done);
    }
    __syncthreads();

    // 6) replicate follower frames from their leader's slot (smem->smem)
    {
        float4* rows4 = (float4*)s_rows;
        #pragma unroll
        for (int i = tid; i < FPB * (ROW_BYTES / 16); i += THREADS) {
            const int f = i >> 7;                 // frame
            const int v = i & 127;                // float4 within row
            const int l = s_lead[f];
            if (l != f)
                rows4[f * 128 + v] = rows4[l * 128 + v];
        }
    }
    __syncthreads();

    // 7) one 64KB bulk store for the whole block
    if (tid == 0) {
        asm volatile("fence.proxy.async.shared::cta;" ::: "memory");
        char* dst = out + ((size_t)b * LR_T + frame_base) * ROW_BYTES;
        asm volatile(
            "cp.async.bulk.global.shared::cta.bulk_group [%0], [%1], %2;"
            :: "l"(dst), "r"(smem_u32(s_rows)), "r"((uint32_t)STAGE_BYTES)
            : "memory");
        asm volatile("cp.async.bulk.commit_group;" ::: "memory");
        asm volatile("cp.async.bulk.wait_group 0;" ::: "memory");
    }
    __syncthreads();
}

extern "C" void kernel_launch(void* const* d_in, const int* in_sizes, int n_in,
                              void* d_out, int out_size)
{
    const char* phoneme   = (const char*)d_in[0];   // (B, N, D) f32
    const int*  durations = (const int*)d_in[1];    // (B, N) i32
    char*       out       = (char*)d_out;           // (B, T, D) f32

    cudaFuncSetAttribute(length_regulator_bulk,
                         cudaFuncAttributeMaxDynamicSharedMemorySize,
                         STAGE_BYTES);

    dim3 grid(LR_T / FPB, LR_B);    // (64, 16) = 1024 blocks
    length_regulator_bulk<<<grid, THREADS, STAGE_BYTES>>>(phoneme, durations, out);
}

// round 9
// speedup vs baseline: 1.1175x; 1.1175x over previous
#include <cuda_runtime.h>
#include <cuda_bf16.h>
#include <cstdint>

// LengthRegulator: out[b, t, :] = phoneme[b, tok(b,t), :]
// tok(b,t) = searchsorted_right(inclusive_cumsum(durations[b,:]), t), clip N-1.
// Shapes (fixed): B=16, N=256, D=512, T=2048. float32.
//
// Stage distinct rows in smem (one-time LDG), then stream stores from smem:
// the 67MB write loop is LDS(29cyc)->STG with no L2-latency dependency.

#define LR_B 16
#define LR_N 256
#define LR_D 512
#define LR_T 2048
#define FPB 16                        // frames per block
#define THREADS 256
#define VPF 128                       // float4 per 2KB row

__global__ __launch_bounds__(THREADS)
void length_regulator_stage(const float4* __restrict__ phoneme4,
                            const int* __restrict__ durations,
                            float4* __restrict__ out4)
{
    __shared__ float4 s_rows[FPB][VPF];   // 32KB worst-case staging
    __shared__ int s_ends[LR_N];
    __shared__ int s_slot_tok[FPB];       // distinct tokens, compacted
    __shared__ int s_frame_slot[FPB];     // frame -> slot
    __shared__ int s_nslots;

    const int b = blockIdx.y;
    const int frame_base = blockIdx.x * FPB;
    const int tid = threadIdx.x;

    // ---- warp 0: scan + search + dedupe ----
    if (tid < 32) {
        const int lane = tid;
        const int4* drow = (const int4*)(durations + b * LR_N);
        int4 a = drow[lane * 2 + 0];
        int4 c = drow[lane * 2 + 1];
        int e0 = a.x;
        int e1 = e0 + a.y;
        int e2 = e1 + a.z;
        int e3 = e2 + a.w;
        int e4 = e3 + c.x;
        int e5 = e4 + c.y;
        int e6 = e5 + c.z;
        int e7 = e6 + c.w;
        int x = e7;
        #pragma unroll
        for (int off = 1; off < 32; off <<= 1) {
            int y = __shfl_up_sync(0xffffffffu, x, off);
            if (lane >= off) x += y;
        }
        const int excl = x - e7;
        s_ends[lane * 8 + 0] = e0 + excl;
        s_ends[lane * 8 + 1] = e1 + excl;
        s_ends[lane * 8 + 2] = e2 + excl;
        s_ends[lane * 8 + 3] = e3 + excl;
        s_ends[lane * 8 + 4] = e4 + excl;
        s_ends[lane * 8 + 5] = e5 + excl;
        s_ends[lane * 8 + 6] = e6 + excl;
        s_ends[lane * 8 + 7] = e7 + excl;
        __syncwarp();

        // lanes 0..15: token of frame frame_base+lane
        int tok = 0;
        if (lane < FPB) {
            const int t = frame_base + lane;
            int lo = 0, hi = LR_N;
            #pragma unroll
            for (int it = 0; it < 9; ++it) {
                if (lo < hi) {
                    int mid = (lo + hi) >> 1;
                    if (s_ends[mid] > t) hi = mid; else lo = mid + 1;
                }
            }
            tok = (lo < LR_N) ? lo : (LR_N - 1);
        }

        // dedupe consecutive equal tokens -> compact slots
        const int prev_tok = __shfl_up_sync(0xffffffffu, tok, 1);
        const bool active = (lane < FPB);
        const bool is_new = active && (lane == 0 || tok != prev_tok);
        const uint32_t new_mask = __ballot_sync(0xffffffffu, is_new);
        const int slot = __popc(new_mask & ((2u << lane) - 1)) - 1;  // run-leader slot
        if (active) {
            s_frame_slot[lane] = slot;
            if (is_new) s_slot_tok[slot] = tok;
        }
        if (lane == 0) s_nslots = __popc(new_mask);
    }
    __syncthreads();

    const int nslots = s_nslots;

    // ---- load distinct rows into smem (coalesced LDG -> STS) ----
    for (int i = tid; i < nslots * VPF; i += THREADS) {
        const int s = i >> 7;
        const int v = i & (VPF - 1);
        s_rows[s][v] = phoneme4[((size_t)b * LR_N + s_slot_tok[s]) * VPF + v];
    }

    // frame->slot into registers while loads are in flight
    int fslot[FPB];
    #pragma unroll
    for (int q = 0; q < FPB / 4; ++q) {
        int4 v = ((const int4*)s_frame_slot)[q];
        fslot[q * 4 + 0] = v.x;
        fslot[q * 4 + 1] = v.y;
        fslot[q * 4 + 2] = v.z;
        fslot[q * 4 + 3] = v.w;
    }
    __syncthreads();

    // ---- stream stores from smem: LDS -> STG, independent iterations ----
    // thread owns column (tid & 127); two frame-halves per iteration.
    const int col = tid & (VPF - 1);
    const int half = tid >> 7;                 // 0 or 1: frames 0..7 / 8..15
    float4* __restrict__ out_b =
        out4 + ((size_t)b * LR_T + frame_base + half * (FPB / 2)) * VPF + col;

    #pragma unroll
    for (int f = 0; f < FPB / 2; ++f) {
        out_b[f * VPF] = s_rows[fslot[half * (FPB / 2) + f]][col];
    }
}

extern "C" void kernel_launch(void* const* d_in, const int* in_sizes, int n_in,
                              void* d_out, int out_size)
{
    const float4* phoneme4  = (const float4*)d_in[0];   // (B, N, D) f32
    const int*    durations = (const int*)d_in[1];      // (B, N) i32
    float4*       out4      = (float4*)d_out;           // (B, T, D) f32

    dim3 grid(LR_T / FPB, LR_B);    // (128, 16) = 2048 blocks
    length_regulator_stage<<<grid, THREADS>>>(phoneme4, durations, out4);
}